// round 10
// baseline (speedup 1.0000x reference)
#include <cuda_runtime.h>
#include <cuda_bf16.h>
#include <cstdint>

#define NHALF   4096
#define NROWS   8192
#define D       128
#define NB      64                        // 128-row blocks
#define NTRI    2080                      // NB*(NB+1)/2 triangular tiles
#define SHIFT2  28.853900817779268f       // 20 * log2(e)
#define LOG2E   1.4426950408889634f
#define SCALE_NORM 3.79828256502352f      // sqrt(log2(e)/0.1), folded into rows

// -------- scratch (__device__ globals; no allocations allowed) --------
__device__ __nv_bfloat16 g_zb[NROWS * D];    // normalized rows * sqrt(log2e/T)
__device__ float g_pos[NHALF];               // pos_i = 2*cos_i/T (fp32)
__device__ float g_partial[NB * NROWS];      // [slot][row] exp row-sum partials
__device__ float g_blk[32];
__device__ int   g_cnt;                      // zero-initialized; self-resetting

__device__ __forceinline__ uint32_t smem_u32(const void* p) {
    uint32_t a;
    asm("{ .reg .u64 t; cvta.to.shared.u64 t, %1; cvt.u32.u64 %0, t; }" : "=r"(a) : "l"(p));
    return a;
}
__device__ __forceinline__ void ldsm4(uint32_t* r, uint32_t addr) {
    asm volatile("ldmatrix.sync.aligned.m8n8.x4.shared.b16 {%0,%1,%2,%3}, [%4];"
                 : "=r"(r[0]), "=r"(r[1]), "=r"(r[2]), "=r"(r[3]) : "r"(addr));
}
__device__ __forceinline__ void mma16816(float* c, const uint32_t* a, const uint32_t* b) {
    asm volatile(
        "mma.sync.aligned.m16n8k16.row.col.f32.bf16.bf16.f32 "
        "{%0,%1,%2,%3}, {%4,%5,%6,%7}, {%8,%9}, {%0,%1,%2,%3};"
        : "+f"(c[0]), "+f"(c[1]), "+f"(c[2]), "+f"(c[3])
        : "r"(a[0]), "r"(a[1]), "r"(a[2]), "r"(a[3]), "r"(b[0]), "r"(b[1]));
}
__device__ __forceinline__ float ex2(float x) {
    float y; asm("ex2.approx.ftz.f32 %0, %1;" : "=f"(y) : "f"(x)); return y;
}

// ---------------- 1) fused normalize(+bf16) + pos ----------------
__global__ void normpos_kernel(const float* __restrict__ z1, const float* __restrict__ z2) {
    int w    = (blockIdx.x * blockDim.x + threadIdx.x) >> 5;  // pair index
    int lane = threadIdx.x & 31;
    if (w >= NHALF) return;
    float4 a = reinterpret_cast<const float4*>(z1 + (size_t)w * D)[lane];
    float4 b = reinterpret_cast<const float4*>(z2 + (size_t)w * D)[lane];
    float aa = a.x * a.x + a.y * a.y + a.z * a.z + a.w * a.w;
    float bb = b.x * b.x + b.y * b.y + b.z * b.z + b.w * b.w;
    float ab = a.x * b.x + a.y * b.y + a.z * b.z + a.w * b.w;
    #pragma unroll
    for (int o = 16; o; o >>= 1) {
        aa += __shfl_xor_sync(0xFFFFFFFFu, aa, o);
        bb += __shfl_xor_sync(0xFFFFFFFFu, bb, o);
        ab += __shfl_xor_sync(0xFFFFFFFFu, ab, o);
    }
    float na = fmaxf(sqrtf(aa), 1e-8f);
    float nb = fmaxf(sqrtf(bb), 1e-8f);
    float sa = SCALE_NORM / na, sb = SCALE_NORM / nb;
    __nv_bfloat162* da = reinterpret_cast<__nv_bfloat162*>(g_zb + (size_t)w * D);
    __nv_bfloat162* db = reinterpret_cast<__nv_bfloat162*>(g_zb + (size_t)(w + NHALF) * D);
    da[lane * 2 + 0] = __floats2bfloat162_rn(a.x * sa, a.y * sa);
    da[lane * 2 + 1] = __floats2bfloat162_rn(a.z * sa, a.w * sa);
    db[lane * 2 + 0] = __floats2bfloat162_rn(b.x * sb, b.y * sb);
    db[lane * 2 + 1] = __floats2bfloat162_rn(b.z * sb, b.w * sb);
    if (lane == 0) g_pos[w] = 20.0f * ab / (na * nb);     // 2*cos/T, T=0.1
}

// ---------------- 2) triangular HMMA tile: row-sums + col-sums ----------------
// CTA: one 128x128 tile (bi <= bj). 8 warps = 4(m) x 2(n), warp tile 32x64.
// K split into two 64-halves; smem per half: A 16KB + B 16KB (static 32KB).
// 128B smem rows (64 bf16), 16B chunk c of row r stored at chunk (c ^ (r&7)).
__global__ __launch_bounds__(256) void gemm_kernel() {
    __shared__ __align__(16) unsigned char smem[32768];   // A:16KB, B at +16384
    const uint32_t sb = smem_u32(smem);
    const int tid  = threadIdx.x;
    const int wid  = tid >> 5;
    const int lane = tid & 31;

    // tile index: first NB blocks take the diagonal (uniform-work tail waves);
    // remaining NTRI-NB blocks enumerate the strict upper triangle bi < bj.
    int bi, bj;
    if (blockIdx.x < NB) {
        bi = bj = blockIdx.x;
    } else {
        int t = blockIdx.x - NB;          // 0 .. 2015, strict triangle of 64
        bj = (int)((sqrtf(8.0f * (float)t + 1.0f) - 1.0f) * 0.5f) + 1;
        while (bj * (bj + 1) / 2 <= t) ++bj;
        while ((bj - 1) * bj / 2 > t) --bj;
        bi = t - (bj - 1) * bj / 2;
    }
    const int base_i = bi * 128;
    const int base_j = bj * 128;
    const bool isdiag = (bi == bj);

    const int warp_m = (wid & 3) * 32;
    const int warp_n = (wid >> 2) * 64;
    const int lr = lane & 7;
    const int q  = lane >> 3;
    const int rowA0 = warp_m + lr + (q & 1) * 8;
    const int ckA   = q >> 1;
    const int rowB0 = warp_n + lr + (q >> 1) * 8;
    const int ckB   = q & 1;

    float acc[2][8][4];
    #pragma unroll
    for (int mt = 0; mt < 2; ++mt)
        #pragma unroll
        for (int nt = 0; nt < 8; ++nt)
            #pragma unroll
            for (int e = 0; e < 4; ++e) acc[mt][nt][e] = 0.0f;

    const int ldr = tid >> 1;            // 0..127
    const int ldc = (tid & 1) * 4;       // chunk base

    #pragma unroll
    for (int kh = 0; kh < 2; ++kh) {
        __syncthreads();
        {
            const uint4* gA = reinterpret_cast<const uint4*>(g_zb + (size_t)(base_i + ldr) * D + kh * 64);
            const uint4* gB = reinterpret_cast<const uint4*>(g_zb + (size_t)(base_j + ldr) * D + kh * 64);
            #pragma unroll
            for (int c = 0; c < 4; ++c) {
                int ch = ldc + c;
                uint32_t off = (uint32_t)ldr * 128u + (uint32_t)((ch ^ (ldr & 7)) * 16);
                *reinterpret_cast<uint4*>(smem + off)          = gA[ch];
                *reinterpret_cast<uint4*>(smem + 16384u + off) = gB[ch];
            }
        }
        __syncthreads();

        #pragma unroll
        for (int ks = 0; ks < 4; ++ks) {
            uint32_t a[2][4], b[8][2];
            #pragma unroll
            for (int mt = 0; mt < 2; ++mt) {
                int r = rowA0 + mt * 16;
                int ch = ks * 2 + ckA;
                ldsm4(a[mt], sb + (uint32_t)r * 128u + (uint32_t)((ch ^ (r & 7)) * 16));
            }
            #pragma unroll
            for (int p = 0; p < 4; ++p) {
                int r = rowB0 + p * 16;
                int ch = ks * 2 + ckB;
                uint32_t tt[4];
                ldsm4(tt, sb + 16384u + (uint32_t)r * 128u + (uint32_t)((ch ^ (r & 7)) * 16));
                b[p * 2 + 0][0] = tt[0]; b[p * 2 + 0][1] = tt[1];
                b[p * 2 + 1][0] = tt[2]; b[p * 2 + 1][1] = tt[3];
            }
            #pragma unroll
            for (int mt = 0; mt < 2; ++mt)
                #pragma unroll
                for (int nt = 0; nt < 8; ++nt)
                    mma16816(acc[mt][nt], a[mt], b[nt]);
        }
    }

    // ---- epilogue ----
    // C frag: c0,c1 -> row l/4, cols 2(l&3)+{0,1}; c2,c3 -> row l/4+8.
    float rs[2][2] = {{0.f, 0.f}, {0.f, 0.f}};
    float cs[8][2];
    #pragma unroll
    for (int nt = 0; nt < 8; ++nt) { cs[nt][0] = 0.f; cs[nt][1] = 0.f; }

    #pragma unroll
    for (int mt = 0; mt < 2; ++mt) {
        const int r0 = base_i + warp_m + mt * 16 + (lane >> 2);
        const int r1 = r0 + 8;
        #pragma unroll
        for (int nt = 0; nt < 8; ++nt) {
            const int gc = base_j + warp_n + nt * 8 + (lane & 3) * 2;
            float e0 = ex2(acc[mt][nt][0] - SHIFT2);
            float e1 = ex2(acc[mt][nt][1] - SHIFT2);
            float e2 = ex2(acc[mt][nt][2] - SHIFT2);
            float e3 = ex2(acc[mt][nt][3] - SHIFT2);
            if (isdiag) {
                if (gc     == r0) e0 = 0.f;
                if (gc + 1 == r0) e1 = 0.f;
                if (gc     == r1) e2 = 0.f;
                if (gc + 1 == r1) e3 = 0.f;
            }
            rs[mt][0] += e0 + e1;
            rs[mt][1] += e2 + e3;
            cs[nt][0] += e0 + e2;
            cs[nt][1] += e1 + e3;
        }
    }

    // row-sums: quad-reduce within warp (lanes sharing a row differ in lane&3)
    #pragma unroll
    for (int mt = 0; mt < 2; ++mt)
        #pragma unroll
        for (int h = 0; h < 2; ++h) {
            float v = rs[mt][h];
            v += __shfl_xor_sync(0xFFFFFFFFu, v, 1);
            v += __shfl_xor_sync(0xFFFFFFFFu, v, 2);
            rs[mt][h] = v;
        }
    // col-sums: reduce across the 8 row-groups of the warp (xor 4,8,16)
    if (!isdiag) {
        #pragma unroll
        for (int nt = 0; nt < 8; ++nt)
            #pragma unroll
            for (int e = 0; e < 2; ++e) {
                float v = cs[nt][e];
                v += __shfl_xor_sync(0xFFFFFFFFu, v, 4);
                v += __shfl_xor_sync(0xFFFFFFFFu, v, 8);
                v += __shfl_xor_sync(0xFFFFFFFFu, v, 16);
                cs[nt][e] = v;
            }
    }

    __syncthreads();   // operand smem no longer needed; reuse for reductions
    float* rowacc = reinterpret_cast<float*>(smem);          // [2][128] per n-half
    float* colacc = reinterpret_cast<float*>(smem) + 256;    // [4][128] per m-group

    if ((lane & 3) == 0) {
        #pragma unroll
        for (int mt = 0; mt < 2; ++mt) {
            int r = warp_m + mt * 16 + (lane >> 2);
            rowacc[(wid >> 2) * 128 + r]     = rs[mt][0];
            rowacc[(wid >> 2) * 128 + r + 8] = rs[mt][1];
        }
    }
    if (!isdiag && lane < 4) {
        #pragma unroll
        for (int nt = 0; nt < 8; ++nt) {
            int col = warp_n + nt * 8 + lane * 2;
            colacc[(wid & 3) * 128 + col]     = cs[nt][0];
            colacc[(wid & 3) * 128 + col + 1] = cs[nt][1];
        }
    }
    __syncthreads();

    if (tid < 128) {
        // slot bj <- rows of block bi (sum of both n-halves)
        g_partial[(size_t)bj * NROWS + base_i + tid] = rowacc[tid] + rowacc[128 + tid];
        if (!isdiag) {
            // slot bi <- rows of block bj (sum of the 4 m-groups)
            float s = colacc[tid] + colacc[128 + tid] + colacc[256 + tid] + colacc[384 + tid];
            g_partial[(size_t)bi * NROWS + base_j + tid] = s;
        }
    }
}

// ---------------- 3) fused reduction (last-block-done) ----------------
__global__ void reduce_kernel(float* __restrict__ out) {
    __shared__ float red[256];
    __shared__ int is_last;
    int r = blockIdx.x * 256 + threadIdx.x;       // 32*256 = 8192 rows
    float s = 0.0f;
    #pragma unroll 8
    for (int p = 0; p < NB; ++p) s += g_partial[(size_t)p * NROWS + r];
    float pv = g_pos[r & (NHALF - 1)];
    s += ex2(pv * LOG2E - SHIFT2);                // the pos logit column
    red[threadIdx.x] = (logf(s) + 20.0f) - pv;    // lse - pos
    __syncthreads();
    #pragma unroll
    for (int o = 128; o; o >>= 1) {
        if (threadIdx.x < o) red[threadIdx.x] += red[threadIdx.x + o];
        __syncthreads();
    }
    if (threadIdx.x == 0) {
        g_blk[blockIdx.x] = red[0];
        __threadfence();
        int done = atomicAdd(&g_cnt, 1);
        is_last = (done == gridDim.x - 1) ? 1 : 0;
    }
    __syncthreads();
    if (is_last) {
        __threadfence();                          // see all g_blk writes
        if (threadIdx.x < 32) {
            float v = g_blk[threadIdx.x];
            #pragma unroll
            for (int o = 16; o; o >>= 1) v += __shfl_xor_sync(0xFFFFFFFFu, v, o);
            if (threadIdx.x == 0) {
                out[0] = v * (1.0f / ((float)NROWS * (float)NROWS));
                g_cnt = 0;                        // reset for graph replay
            }
        }
    }
}

// ---------------- launcher ----------------
extern "C" void kernel_launch(void* const* d_in, const int* in_sizes, int n_in,
                              void* d_out, int out_size) {
    const float* z1 = (const float*)d_in[0];
    const float* z2 = (const float*)d_in[1];
    float* out = (float*)d_out;
    (void)in_sizes; (void)n_in; (void)out_size;

    normpos_kernel<<<NHALF / 8, 256>>>(z1, z2);
    gemm_kernel<<<NTRI, 256>>>();
    reduce_kernel<<<32, 256>>>(out);
}